// round 14
// baseline (speedup 1.0000x reference)
#include <cstdint>
#include <cuda_runtime.h>
#include <cuda_bf16.h>
#include <mma.h>
#include <math.h>

using namespace nvcuda;

#define DD 256

#define LDA 72     // A stage stride (bf16): 64 + 8 pad
#define LDB 136    // B stage stride (bf16): 128 + 8 pad
#define LDS 132    // epilogue staging stride (f32)

// 2-stage pipeline arena: stage = A[64x64] + B[64x128] (bf16, padded)
#define ST_A     9216             // 64*72*2
#define ST_BYTES 26624            // + 64*136*2
#define SMEM_PIPE (2 * ST_BYTES)  // 53248; epilogue staging 64*132*4 = 33792 fits

__device__ __nv_bfloat16 g_wfcb[256 * 1024];     // [k=256,  n=1024]
__device__ __nv_bfloat16 g_wprb[1024 * 256];     // [k=1024, n=256]
__device__ float         g_yo[1024 * DD];
__device__ __nv_bfloat16 g_xb[131072 * 256];           // x3 bf16
__device__ __nv_bfloat16 g_hb[(size_t)131072 * 1024];  // gelu(h) bf16

// ---------------------------------------------------------------------------
__device__ __forceinline__ void cp16(void* sdst, const void* gsrc) {
    unsigned s = (unsigned)__cvta_generic_to_shared(sdst);
    asm volatile("cp.async.cg.shared.global [%0], [%1], 16;" :: "r"(s), "l"(gsrc));
}
#define CP_COMMIT() asm volatile("cp.async.commit_group;" ::: "memory")
#define CP_WAIT1()  asm volatile("cp.async.wait_group 1;" ::: "memory")
#define CP_WAIT0()  asm volatile("cp.async.wait_group 0;" ::: "memory")

__device__ __forceinline__ float gelu_exact(float v) {
    return 0.5f * v * (1.f + erff(v * 0.70710678118654752f));
}

// ---------------------------------------------------------------------------
// prep: blocks 0-255 convert weights fp32->bf16; blocks 256-511 compute yo.
// yo[b,a,:] = ((cx @ wkv)[:, D:2D] + bkv[D:2D]) @ wo + bo
// ---------------------------------------------------------------------------
__global__ void prep_kernel(const float* __restrict__ wfc, const float* __restrict__ wpr,
                            const float* __restrict__ cx,  const float* __restrict__ wkv,
                            const float* __restrict__ bkv, const float* __restrict__ wo,
                            const float* __restrict__ bo) {
    __shared__ float sCX[4][DD];
    __shared__ float sV[4][DD];
    int tid = threadIdx.x;
    if (blockIdx.x < 256) {
        int i = blockIdx.x * 256 + tid;
        float4 a = ((const float4*)wfc)[i];
        ((__nv_bfloat162*)g_wfcb)[i * 2]     = __floats2bfloat162_rn(a.x, a.y);
        ((__nv_bfloat162*)g_wfcb)[i * 2 + 1] = __floats2bfloat162_rn(a.z, a.w);
        float4 b = ((const float4*)wpr)[i];
        ((__nv_bfloat162*)g_wprb)[i * 2]     = __floats2bfloat162_rn(b.x, b.y);
        ((__nv_bfloat162*)g_wprb)[i * 2 + 1] = __floats2bfloat162_rn(b.z, b.w);
        return;
    }
    int r0 = (blockIdx.x - 256) * 4;
    #pragma unroll
    for (int i = 0; i < 4; i++) sCX[i][tid] = cx[(r0 + i) * DD + tid];
    __syncthreads();
    float acc[4];
    #pragma unroll
    for (int i = 0; i < 4; i++) acc[i] = bkv[DD + tid];
    for (int c = 0; c < DD; c++) {
        float w = wkv[c * 512 + DD + tid];
        #pragma unroll
        for (int i = 0; i < 4; i++) acc[i] += sCX[i][c] * w;
    }
    #pragma unroll
    for (int i = 0; i < 4; i++) sV[i][tid] = acc[i];
    __syncthreads();
    float a2[4];
    #pragma unroll
    for (int i = 0; i < 4; i++) a2[i] = bo[tid];
    for (int k = 0; k < DD; k++) {
        float w = wo[k * DD + tid];
        #pragma unroll
        for (int i = 0; i < 4; i++) a2[i] += sV[i][k] * w;
    }
    #pragma unroll
    for (int i = 0; i < 4; i++) g_yo[(r0 + i) * DD + tid] = a2[i];
}

// ---------------------------------------------------------------------------
// LN: x3 = LN2(LN1(x)+yo) -> out (fp32 residual base) and g_xb (bf16 GEMM A)
// ---------------------------------------------------------------------------
__global__ void __launch_bounds__(256)
ln_kernel(const float* __restrict__ x,
          const float* __restrict__ ln1w, const float* __restrict__ ln1b,
          const float* __restrict__ ln2w, const float* __restrict__ ln2b,
          float* __restrict__ out) {
    int warp = threadIdx.x >> 5;
    int lane = threadIdx.x & 31;
    size_t row = (size_t)blockIdx.x * 8 + warp;

    float lw1[8], lb1[8], lw2[8], lb2[8], yo[8];
    {
        float4 a, b;
        a = ((const float4*)ln1w)[lane*2]; b = ((const float4*)ln1w)[lane*2+1];
        lw1[0]=a.x;lw1[1]=a.y;lw1[2]=a.z;lw1[3]=a.w;lw1[4]=b.x;lw1[5]=b.y;lw1[6]=b.z;lw1[7]=b.w;
        a = ((const float4*)ln1b)[lane*2]; b = ((const float4*)ln1b)[lane*2+1];
        lb1[0]=a.x;lb1[1]=a.y;lb1[2]=a.z;lb1[3]=a.w;lb1[4]=b.x;lb1[5]=b.y;lb1[6]=b.z;lb1[7]=b.w;
        a = ((const float4*)ln2w)[lane*2]; b = ((const float4*)ln2w)[lane*2+1];
        lw2[0]=a.x;lw2[1]=a.y;lw2[2]=a.z;lw2[3]=a.w;lw2[4]=b.x;lw2[5]=b.y;lw2[6]=b.z;lw2[7]=b.w;
        a = ((const float4*)ln2b)[lane*2]; b = ((const float4*)ln2b)[lane*2+1];
        lb2[0]=a.x;lb2[1]=a.y;lb2[2]=a.z;lb2[3]=a.w;lb2[4]=b.x;lb2[5]=b.y;lb2[6]=b.z;lb2[7]=b.w;
        const float* yor = g_yo + (row >> 7) * DD;
        a = ((const float4*)yor)[lane*2]; b = ((const float4*)yor)[lane*2+1];
        yo[0]=a.x;yo[1]=a.y;yo[2]=a.z;yo[3]=a.w;yo[4]=b.x;yo[5]=b.y;yo[6]=b.z;yo[7]=b.w;
    }
    const float4* xr = (const float4*)(x + row * DD);
    float v[8];
    { float4 u0 = xr[lane*2], u1 = xr[lane*2+1];
      v[0]=u0.x;v[1]=u0.y;v[2]=u0.z;v[3]=u0.w;v[4]=u1.x;v[5]=u1.y;v[6]=u1.z;v[7]=u1.w; }
    float s = 0.f, q = 0.f;
    #pragma unroll
    for (int j = 0; j < 8; j++) { s += v[j]; q += v[j]*v[j]; }
    #pragma unroll
    for (int o = 16; o > 0; o >>= 1) { s += __shfl_xor_sync(~0u,s,o); q += __shfl_xor_sync(~0u,q,o); }
    float mu = s * (1.f/DD);
    float rs = rsqrtf(q * (1.f/DD) - mu*mu + 1e-5f);
    float tv[8]; s = 0.f; q = 0.f;
    #pragma unroll
    for (int j = 0; j < 8; j++) {
        tv[j] = (v[j]-mu)*rs*lw1[j] + lb1[j] + yo[j];
        s += tv[j]; q += tv[j]*tv[j];
    }
    #pragma unroll
    for (int o = 16; o > 0; o >>= 1) { s += __shfl_xor_sync(~0u,s,o); q += __shfl_xor_sync(~0u,q,o); }
    float mu2 = s * (1.f/DD);
    float rs2 = rsqrtf(q * (1.f/DD) - mu2*mu2 + 1e-5f);
    #pragma unroll
    for (int j = 0; j < 8; j++) v[j] = (tv[j]-mu2)*rs2*lw2[j] + lb2[j];

    float* orow = out + row * DD;
    ((float4*)orow)[lane*2]   = make_float4(v[0],v[1],v[2],v[3]);
    ((float4*)orow)[lane*2+1] = make_float4(v[4],v[5],v[6],v[7]);

    __nv_bfloat162 p0 = __floats2bfloat162_rn(v[0],v[1]);
    __nv_bfloat162 p1 = __floats2bfloat162_rn(v[2],v[3]);
    __nv_bfloat162 p2 = __floats2bfloat162_rn(v[4],v[5]);
    __nv_bfloat162 p3 = __floats2bfloat162_rn(v[6],v[7]);
    uint4 pk;
    pk.x = *(unsigned*)&p0; pk.y = *(unsigned*)&p1; pk.z = *(unsigned*)&p2; pk.w = *(unsigned*)&p3;
    *(uint4*)(g_xb + row * DD + lane * 8) = pk;
}

// ---------------------------------------------------------------------------
// GEMM core: 64x128 CTA tile, 128 threads (4 warps), K-chunk 64, 2 stages.
// Warp tile 32x64. B-fragments register-double-buffered across ks steps.
// ---------------------------------------------------------------------------
#define GEMM_COMPUTE(sm, st)                                                      \
    {                                                                             \
        const __nv_bfloat16* Ab = (const __nv_bfloat16*)((sm) + (st) * ST_BYTES) + (wm * 32) * LDA; \
        const __nv_bfloat16* Bb = (const __nv_bfloat16*)((sm) + (st) * ST_BYTES + ST_A) + wn * 64;  \
        wmma::fragment<wmma::matrix_b, 16, 16, 16, __nv_bfloat16, wmma::row_major> bf[2][4]; \
        _Pragma("unroll")                                                         \
        for (int n = 0; n < 4; n++)                                               \
            wmma::load_matrix_sync(bf[0][n], Bb + n * 16, LDB);                   \
        _Pragma("unroll")                                                         \
        for (int kk = 0; kk < 4; kk++) {                                          \
            if (kk < 3) {                                                         \
                _Pragma("unroll")                                                 \
                for (int n = 0; n < 4; n++)                                       \
                    wmma::load_matrix_sync(bf[(kk + 1) & 1][n],                   \
                                           Bb + (kk + 1) * 16 * LDB + n * 16, LDB); \
            }                                                                     \
            wmma::fragment<wmma::matrix_a, 16, 16, 16, __nv_bfloat16, wmma::row_major> a0, a1; \
            wmma::load_matrix_sync(a0, Ab + kk * 16, LDA);                        \
            wmma::load_matrix_sync(a1, Ab + 16 * LDA + kk * 16, LDA);             \
            _Pragma("unroll")                                                     \
            for (int n = 0; n < 4; n++) {                                         \
                wmma::mma_sync(c0[n], a0, bf[kk & 1][n], c0[n]);                  \
                wmma::mma_sync(c1[n], a1, bf[kk & 1][n], c1[n]);                  \
            }                                                                     \
        }                                                                         \
    }

// stage fill: A[64x64] from (abase + (row0+r)*astr + kt*64), B[64x128] from (bbase + (kt*64+r)*bstr + col0)
#define GEMM_FILL(sm, st, kt, abase, astr, bbase, bstr)                           \
    {                                                                             \
        char* A = (sm) + (st) * ST_BYTES;                                         \
        char* B = A + ST_A;                                                       \
        _Pragma("unroll")                                                         \
        for (int t = 0; t < 4; t++) {                                             \
            int idx = tid + t * 128, r = idx >> 3, qq = idx & 7;                  \
            cp16(A + (r * LDA + qq * 8) * 2, (abase) + (size_t)(row0 + r) * (astr) + (kt) * 64 + qq * 8); \
        }                                                                         \
        _Pragma("unroll")                                                         \
        for (int t = 0; t < 8; t++) {                                             \
            int idx = tid + t * 128, r = idx >> 4, qq = idx & 15;                 \
            cp16(B + (r * LDB + qq * 8) * 2, (bbase) + (size_t)((kt) * 64 + r) * (bstr) + col0 + qq * 8); \
        }                                                                         \
    }

// ---------------------------------------------------------------------------
// GEMM1: g_hb = gelu(g_xb @ Wfc + bfc)   [131072,256] x [256,1024], NCH=4
// ---------------------------------------------------------------------------
__global__ void __launch_bounds__(128, 3)
gemm1_kernel(const float* __restrict__ bfc) {
    extern __shared__ __align__(16) char sm[];
    int tid  = threadIdx.x;
    int warp = tid >> 5;
    int wm = warp & 1, wn = warp >> 1;
    size_t row0 = (size_t)(blockIdx.x >> 3) * 64;
    int col0 = (blockIdx.x & 7) * 128;

    wmma::fragment<wmma::accumulator, 16, 16, 16, float> c0[4], c1[4];
    #pragma unroll
    for (int n = 0; n < 4; n++) { wmma::fill_fragment(c0[n], 0.f); wmma::fill_fragment(c1[n], 0.f); }

    GEMM_FILL(sm, 0, 0, g_xb, 256, g_wfcb, 1024); CP_COMMIT();
    GEMM_FILL(sm, 1, 1, g_xb, 256, g_wfcb, 1024); CP_COMMIT();

    #pragma unroll
    for (int kt = 0; kt < 4; kt++) {
        CP_WAIT1();
        __syncthreads();
        GEMM_COMPUTE(sm, kt & 1);
        __syncthreads();
        if (kt + 2 < 4) { GEMM_FILL(sm, kt & 1, kt + 2, g_xb, 256, g_wfcb, 1024); }
        CP_COMMIT();
    }

    // epilogue: bias + gelu -> bf16 g_hb
    CP_WAIT0();
    __syncthreads();
    float* S = (float*)sm;
    float* Sp = S + (wm * 32) * LDS + wn * 64;
    #pragma unroll
    for (int n = 0; n < 4; n++) {
        wmma::store_matrix_sync(Sp + n * 16,            c0[n], LDS, wmma::mem_row_major);
        wmma::store_matrix_sync(Sp + 16 * LDS + n * 16, c1[n], LDS, wmma::mem_row_major);
    }
    __syncthreads();
    #pragma unroll
    for (int j = 0; j < 8; j++) {
        int cc = tid + j * 128, r = cc >> 4, q = cc & 15;
        const float* Sr = S + r * LDS + q * 8;
        float4 f0 = *(const float4*)(Sr);
        float4 f1 = *(const float4*)(Sr + 4);
        const float* bf = bfc + col0 + q * 8;
        f0.x = gelu_exact(f0.x + bf[0]); f0.y = gelu_exact(f0.y + bf[1]);
        f0.z = gelu_exact(f0.z + bf[2]); f0.w = gelu_exact(f0.w + bf[3]);
        f1.x = gelu_exact(f1.x + bf[4]); f1.y = gelu_exact(f1.y + bf[5]);
        f1.z = gelu_exact(f1.z + bf[6]); f1.w = gelu_exact(f1.w + bf[7]);
        __nv_bfloat162 q0 = __floats2bfloat162_rn(f0.x, f0.y);
        __nv_bfloat162 q1 = __floats2bfloat162_rn(f0.z, f0.w);
        __nv_bfloat162 q2 = __floats2bfloat162_rn(f1.x, f1.y);
        __nv_bfloat162 q3 = __floats2bfloat162_rn(f1.z, f1.w);
        uint4 pk;
        pk.x = *(unsigned*)&q0; pk.y = *(unsigned*)&q1;
        pk.z = *(unsigned*)&q2; pk.w = *(unsigned*)&q3;
        *(uint4*)(g_hb + (row0 + r) * 1024 + col0 + q * 8) = pk;
    }
}

// ---------------------------------------------------------------------------
// GEMM2: out = x3(out) + g_hb @ Wpr + bpr   [131072,1024] x [1024,256], NCH=16
// ---------------------------------------------------------------------------
__global__ void __launch_bounds__(128, 3)
gemm2_kernel(const float* __restrict__ bpr, float* __restrict__ out) {
    extern __shared__ __align__(16) char sm[];
    int tid  = threadIdx.x;
    int warp = tid >> 5;
    int wm = warp & 1, wn = warp >> 1;
    size_t row0 = (size_t)(blockIdx.x >> 1) * 64;
    int col0 = (blockIdx.x & 1) * 128;

    wmma::fragment<wmma::accumulator, 16, 16, 16, float> c0[4], c1[4];
    #pragma unroll
    for (int n = 0; n < 4; n++) { wmma::fill_fragment(c0[n], 0.f); wmma::fill_fragment(c1[n], 0.f); }

    GEMM_FILL(sm, 0, 0, g_hb, 1024, g_wprb, 256); CP_COMMIT();
    GEMM_FILL(sm, 1, 1, g_hb, 1024, g_wprb, 256); CP_COMMIT();

    for (int kt = 0; kt < 16; kt++) {
        CP_WAIT1();
        __syncthreads();
        GEMM_COMPUTE(sm, kt & 1);
        __syncthreads();
        if (kt + 2 < 16) { GEMM_FILL(sm, kt & 1, kt + 2, g_hb, 1024, g_wprb, 256); }
        CP_COMMIT();
    }

    // epilogue: out = x3(out) + acc + bpr
    CP_WAIT0();
    __syncthreads();
    float* S = (float*)sm;
    float* Sp = S + (wm * 32) * LDS + wn * 64;
    #pragma unroll
    for (int n = 0; n < 4; n++) {
        wmma::store_matrix_sync(Sp + n * 16,            c0[n], LDS, wmma::mem_row_major);
        wmma::store_matrix_sync(Sp + 16 * LDS + n * 16, c1[n], LDS, wmma::mem_row_major);
    }
    __syncthreads();
    #pragma unroll
    for (int j = 0; j < 8; j++) {
        int cc = tid + j * 128, r = cc >> 4, q = cc & 15;
        const float* Sr = S + r * LDS + q * 8;
        float* og = out + (row0 + r) * DD + col0 + q * 8;
        const float* bp = bpr + col0 + q * 8;
        float4 f0 = *(const float4*)(Sr);
        float4 f1 = *(const float4*)(Sr + 4);
        float4 x0 = *(const float4*)(og);
        float4 x1 = *(const float4*)(og + 4);
        f0.x += x0.x + bp[0]; f0.y += x0.y + bp[1]; f0.z += x0.z + bp[2]; f0.w += x0.w + bp[3];
        f1.x += x1.x + bp[4]; f1.y += x1.y + bp[5]; f1.z += x1.z + bp[6]; f1.w += x1.w + bp[7];
        *(float4*)(og)     = f0;
        *(float4*)(og + 4) = f1;
    }
}

// ---------------------------------------------------------------------------
extern "C" void kernel_launch(void* const* d_in, const int* in_sizes, int n_in,
                              void* d_out, int out_size) {
    const float* x    = (const float*)d_in[0];
    const float* cx   = (const float*)d_in[1];
    const float* ln1w = (const float*)d_in[2];
    const float* ln1b = (const float*)d_in[3];
    // d_in[4]=wq, d_in[5]=bq: unused (uniform softmax over equal logits; V constant over keys)
    const float* wkv  = (const float*)d_in[6];
    const float* bkv  = (const float*)d_in[7];
    const float* wo   = (const float*)d_in[8];
    const float* bo   = (const float*)d_in[9];
    const float* ln2w = (const float*)d_in[10];
    const float* ln2b = (const float*)d_in[11];
    const float* wfc  = (const float*)d_in[12];
    const float* bfc  = (const float*)d_in[13];
    const float* wpr  = (const float*)d_in[14];
    const float* bpr  = (const float*)d_in[15];
    float* out = (float*)d_out;

    cudaFuncSetAttribute(gemm1_kernel, cudaFuncAttributeMaxDynamicSharedMemorySize, SMEM_PIPE);
    cudaFuncSetAttribute(gemm2_kernel, cudaFuncAttributeMaxDynamicSharedMemorySize, SMEM_PIPE);

    prep_kernel<<<512, 256>>>(wfc, wpr, cx, wkv, bkv, wo, bo);
    ln_kernel<<<16384, 256>>>(x, ln1w, ln1b, ln2w, ln2b, out);
    gemm1_kernel<<<16384, 128, SMEM_PIPE>>>(bfc);
    gemm2_kernel<<<4096, 128, SMEM_PIPE>>>(bpr, out);
}

// round 15
// speedup vs baseline: 1.0771x; 1.0771x over previous
#include <cstdint>
#include <cuda_runtime.h>
#include <cuda_bf16.h>
#include <mma.h>
#include <math.h>

using namespace nvcuda;

#define DD 256

#define LDA 72     // A stage stride (bf16): 64 + 8 pad
#define LDB 136    // B stage stride (bf16): 128 + 8 pad
#define LDS 132    // epilogue staging stride (f32)

// 2-stage pipeline arena: stage = A[128x64] + B[64x128] (bf16, padded)
#define ST_A     18432            // 128*72*2
#define ST_BYTES 35840            // + 64*136*2
#define SMEM_PIPE (2 * ST_BYTES)  // 71680; epilogue staging 128*132*4 = 67584 fits

__device__ __nv_bfloat16 g_wfcb[256 * 1024];     // [k=256,  n=1024]
__device__ __nv_bfloat16 g_wprb[1024 * 256];     // [k=1024, n=256]
__device__ float         g_yo[1024 * DD];
__device__ __nv_bfloat16 g_xb[131072 * 256];           // x3 bf16
__device__ __nv_bfloat16 g_hb[(size_t)131072 * 1024];  // gelu(h) bf16

// ---------------------------------------------------------------------------
__device__ __forceinline__ void cp16(void* sdst, const void* gsrc) {
    unsigned s = (unsigned)__cvta_generic_to_shared(sdst);
    asm volatile("cp.async.cg.shared.global [%0], [%1], 16;" :: "r"(s), "l"(gsrc));
}
#define CP_COMMIT() asm volatile("cp.async.commit_group;" ::: "memory")
#define CP_WAIT1()  asm volatile("cp.async.wait_group 1;" ::: "memory")
#define CP_WAIT0()  asm volatile("cp.async.wait_group 0;" ::: "memory")

__device__ __forceinline__ float gelu_exact(float v) {
    return 0.5f * v * (1.f + erff(v * 0.70710678118654752f));
}

// ---------------------------------------------------------------------------
// prep: blocks 0-255 convert weights fp32->bf16; blocks 256-511 compute yo.
// yo[b,a,:] = ((cx @ wkv)[:, D:2D] + bkv[D:2D]) @ wo + bo
// ---------------------------------------------------------------------------
__global__ void prep_kernel(const float* __restrict__ wfc, const float* __restrict__ wpr,
                            const float* __restrict__ cx,  const float* __restrict__ wkv,
                            const float* __restrict__ bkv, const float* __restrict__ wo,
                            const float* __restrict__ bo) {
    __shared__ float sCX[4][DD];
    __shared__ float sV[4][DD];
    int tid = threadIdx.x;
    if (blockIdx.x < 256) {
        int i = blockIdx.x * 256 + tid;
        float4 a = ((const float4*)wfc)[i];
        ((__nv_bfloat162*)g_wfcb)[i * 2]     = __floats2bfloat162_rn(a.x, a.y);
        ((__nv_bfloat162*)g_wfcb)[i * 2 + 1] = __floats2bfloat162_rn(a.z, a.w);
        float4 b = ((const float4*)wpr)[i];
        ((__nv_bfloat162*)g_wprb)[i * 2]     = __floats2bfloat162_rn(b.x, b.y);
        ((__nv_bfloat162*)g_wprb)[i * 2 + 1] = __floats2bfloat162_rn(b.z, b.w);
        return;
    }
    int r0 = (blockIdx.x - 256) * 4;
    #pragma unroll
    for (int i = 0; i < 4; i++) sCX[i][tid] = cx[(r0 + i) * DD + tid];
    __syncthreads();
    float acc[4];
    #pragma unroll
    for (int i = 0; i < 4; i++) acc[i] = bkv[DD + tid];
    for (int c = 0; c < DD; c++) {
        float w = wkv[c * 512 + DD + tid];
        #pragma unroll
        for (int i = 0; i < 4; i++) acc[i] += sCX[i][c] * w;
    }
    #pragma unroll
    for (int i = 0; i < 4; i++) sV[i][tid] = acc[i];
    __syncthreads();
    float a2[4];
    #pragma unroll
    for (int i = 0; i < 4; i++) a2[i] = bo[tid];
    for (int k = 0; k < DD; k++) {
        float w = wo[k * DD + tid];
        #pragma unroll
        for (int i = 0; i < 4; i++) a2[i] += sV[i][k] * w;
    }
    #pragma unroll
    for (int i = 0; i < 4; i++) g_yo[(r0 + i) * DD + tid] = a2[i];
}

// ---------------------------------------------------------------------------
// LN: x3 = LN2(LN1(x)+yo) -> out (fp32 residual base) and g_xb (bf16 GEMM A)
// ---------------------------------------------------------------------------
__global__ void __launch_bounds__(256)
ln_kernel(const float* __restrict__ x,
          const float* __restrict__ ln1w, const float* __restrict__ ln1b,
          const float* __restrict__ ln2w, const float* __restrict__ ln2b,
          float* __restrict__ out) {
    int warp = threadIdx.x >> 5;
    int lane = threadIdx.x & 31;
    size_t row = (size_t)blockIdx.x * 8 + warp;

    float lw1[8], lb1[8], lw2[8], lb2[8], yo[8];
    {
        float4 a, b;
        a = ((const float4*)ln1w)[lane*2]; b = ((const float4*)ln1w)[lane*2+1];
        lw1[0]=a.x;lw1[1]=a.y;lw1[2]=a.z;lw1[3]=a.w;lw1[4]=b.x;lw1[5]=b.y;lw1[6]=b.z;lw1[7]=b.w;
        a = ((const float4*)ln1b)[lane*2]; b = ((const float4*)ln1b)[lane*2+1];
        lb1[0]=a.x;lb1[1]=a.y;lb1[2]=a.z;lb1[3]=a.w;lb1[4]=b.x;lb1[5]=b.y;lb1[6]=b.z;lb1[7]=b.w;
        a = ((const float4*)ln2w)[lane*2]; b = ((const float4*)ln2w)[lane*2+1];
        lw2[0]=a.x;lw2[1]=a.y;lw2[2]=a.z;lw2[3]=a.w;lw2[4]=b.x;lw2[5]=b.y;lw2[6]=b.z;lw2[7]=b.w;
        a = ((const float4*)ln2b)[lane*2]; b = ((const float4*)ln2b)[lane*2+1];
        lb2[0]=a.x;lb2[1]=a.y;lb2[2]=a.z;lb2[3]=a.w;lb2[4]=b.x;lb2[5]=b.y;lb2[6]=b.z;lb2[7]=b.w;
        const float* yor = g_yo + (row >> 7) * DD;
        a = ((const float4*)yor)[lane*2]; b = ((const float4*)yor)[lane*2+1];
        yo[0]=a.x;yo[1]=a.y;yo[2]=a.z;yo[3]=a.w;yo[4]=b.x;yo[5]=b.y;yo[6]=b.z;yo[7]=b.w;
    }
    const float4* xr = (const float4*)(x + row * DD);
    float v[8];
    { float4 u0 = xr[lane*2], u1 = xr[lane*2+1];
      v[0]=u0.x;v[1]=u0.y;v[2]=u0.z;v[3]=u0.w;v[4]=u1.x;v[5]=u1.y;v[6]=u1.z;v[7]=u1.w; }
    float s = 0.f, q = 0.f;
    #pragma unroll
    for (int j = 0; j < 8; j++) { s += v[j]; q += v[j]*v[j]; }
    #pragma unroll
    for (int o = 16; o > 0; o >>= 1) { s += __shfl_xor_sync(~0u,s,o); q += __shfl_xor_sync(~0u,q,o); }
    float mu = s * (1.f/DD);
    float rs = rsqrtf(q * (1.f/DD) - mu*mu + 1e-5f);
    float tv[8]; s = 0.f; q = 0.f;
    #pragma unroll
    for (int j = 0; j < 8; j++) {
        tv[j] = (v[j]-mu)*rs*lw1[j] + lb1[j] + yo[j];
        s += tv[j]; q += tv[j]*tv[j];
    }
    #pragma unroll
    for (int o = 16; o > 0; o >>= 1) { s += __shfl_xor_sync(~0u,s,o); q += __shfl_xor_sync(~0u,q,o); }
    float mu2 = s * (1.f/DD);
    float rs2 = rsqrtf(q * (1.f/DD) - mu2*mu2 + 1e-5f);
    #pragma unroll
    for (int j = 0; j < 8; j++) v[j] = (tv[j]-mu2)*rs2*lw2[j] + lb2[j];

    float* orow = out + row * DD;
    ((float4*)orow)[lane*2]   = make_float4(v[0],v[1],v[2],v[3]);
    ((float4*)orow)[lane*2+1] = make_float4(v[4],v[5],v[6],v[7]);

    __nv_bfloat162 p0 = __floats2bfloat162_rn(v[0],v[1]);
    __nv_bfloat162 p1 = __floats2bfloat162_rn(v[2],v[3]);
    __nv_bfloat162 p2 = __floats2bfloat162_rn(v[4],v[5]);
    __nv_bfloat162 p3 = __floats2bfloat162_rn(v[6],v[7]);
    uint4 pk;
    pk.x = *(unsigned*)&p0; pk.y = *(unsigned*)&p1; pk.z = *(unsigned*)&p2; pk.w = *(unsigned*)&p3;
    *(uint4*)(g_xb + row * DD + lane * 8) = pk;
}

// ---------------------------------------------------------------------------
// GEMM core: 128x128 CTA tile, 128 threads (4 warps), K-chunk 64, 2 stages.
// Warp tile 64x64: wm = warp&1 (64-row strip), wn = warp>>1 (64-col half).
// 4 A-frags + 4 B-frags feed 16 mmas per ks step (0.0625 B/MAC on smem).
// ---------------------------------------------------------------------------
#define GEMM_COMPUTE(sm, st)                                                      \
    {                                                                             \
        const __nv_bfloat16* Ab = (const __nv_bfloat16*)((sm) + (st) * ST_BYTES) + (wm * 64) * LDA; \
        const __nv_bfloat16* Bb = (const __nv_bfloat16*)((sm) + (st) * ST_BYTES + ST_A) + wn * 64;  \
        _Pragma("unroll")                                                         \
        for (int ks = 0; ks < 64; ks += 16) {                                     \
            wmma::fragment<wmma::matrix_a, 16, 16, 16, __nv_bfloat16, wmma::row_major> a[4]; \
            wmma::fragment<wmma::matrix_b, 16, 16, 16, __nv_bfloat16, wmma::row_major> b[4]; \
            _Pragma("unroll")                                                     \
            for (int m = 0; m < 4; m++)                                           \
                wmma::load_matrix_sync(a[m], Ab + (m * 16) * LDA + ks, LDA);      \
            _Pragma("unroll")                                                     \
            for (int n = 0; n < 4; n++)                                           \
                wmma::load_matrix_sync(b[n], Bb + ks * LDB + n * 16, LDB);        \
            _Pragma("unroll")                                                     \
            for (int m = 0; m < 4; m++)                                           \
                _Pragma("unroll")                                                 \
                for (int n = 0; n < 4; n++)                                       \
                    wmma::mma_sync(c[m][n], a[m], b[n], c[m][n]);                 \
        }                                                                         \
    }

// stage fill: A[128x64] from (abase + (row0+r)*astr + kt*64), B[64x128] from (bbase + (kt*64+r)*bstr + col0)
#define GEMM_FILL(sm, st, kt, abase, astr, bbase, bstr)                           \
    {                                                                             \
        char* A = (sm) + (st) * ST_BYTES;                                         \
        char* B = A + ST_A;                                                       \
        _Pragma("unroll")                                                         \
        for (int t = 0; t < 8; t++) {                                             \
            int idx = tid + t * 128, r = idx >> 3, qq = idx & 7;                  \
            cp16(A + (r * LDA + qq * 8) * 2, (abase) + (size_t)(row0 + r) * (astr) + (kt) * 64 + qq * 8); \
        }                                                                         \
        _Pragma("unroll")                                                         \
        for (int t = 0; t < 8; t++) {                                             \
            int idx = tid + t * 128, r = idx >> 4, qq = idx & 15;                 \
            cp16(B + (r * LDB + qq * 8) * 2, (bbase) + (size_t)((kt) * 64 + r) * (bstr) + col0 + qq * 8); \
        }                                                                         \
    }

// ---------------------------------------------------------------------------
// GEMM1: g_hb = gelu(g_xb @ Wfc + bfc)   [131072,256] x [256,1024], NCH=4
// ---------------------------------------------------------------------------
__global__ void __launch_bounds__(128, 2)
gemm1_kernel(const float* __restrict__ bfc) {
    extern __shared__ __align__(16) char sm[];
    int tid  = threadIdx.x;
    int warp = tid >> 5;
    int wm = warp & 1, wn = warp >> 1;
    size_t row0 = (size_t)(blockIdx.x >> 3) * 128;
    int col0 = (blockIdx.x & 7) * 128;

    wmma::fragment<wmma::accumulator, 16, 16, 16, float> c[4][4];
    #pragma unroll
    for (int m = 0; m < 4; m++)
        #pragma unroll
        for (int n = 0; n < 4; n++) wmma::fill_fragment(c[m][n], 0.f);

    GEMM_FILL(sm, 0, 0, g_xb, 256, g_wfcb, 1024); CP_COMMIT();
    GEMM_FILL(sm, 1, 1, g_xb, 256, g_wfcb, 1024); CP_COMMIT();

    #pragma unroll
    for (int kt = 0; kt < 4; kt++) {
        CP_WAIT1();
        __syncthreads();
        GEMM_COMPUTE(sm, kt & 1);
        __syncthreads();
        if (kt + 2 < 4) { GEMM_FILL(sm, kt & 1, kt + 2, g_xb, 256, g_wfcb, 1024); }
        CP_COMMIT();
    }

    // epilogue: bias + gelu -> bf16 g_hb
    CP_WAIT0();
    __syncthreads();
    float* S = (float*)sm;
    float* Sp = S + (wm * 64) * LDS + wn * 64;
    #pragma unroll
    for (int m = 0; m < 4; m++)
        #pragma unroll
        for (int n = 0; n < 4; n++)
            wmma::store_matrix_sync(Sp + (m * 16) * LDS + n * 16, c[m][n], LDS, wmma::mem_row_major);
    __syncthreads();
    #pragma unroll
    for (int j = 0; j < 16; j++) {
        int cc = tid + j * 128, r = cc >> 4, q = cc & 15;
        const float* Sr = S + r * LDS + q * 8;
        float4 f0 = *(const float4*)(Sr);
        float4 f1 = *(const float4*)(Sr + 4);
        const float* bf = bfc + col0 + q * 8;
        f0.x = gelu_exact(f0.x + bf[0]); f0.y = gelu_exact(f0.y + bf[1]);
        f0.z = gelu_exact(f0.z + bf[2]); f0.w = gelu_exact(f0.w + bf[3]);
        f1.x = gelu_exact(f1.x + bf[4]); f1.y = gelu_exact(f1.y + bf[5]);
        f1.z = gelu_exact(f1.z + bf[6]); f1.w = gelu_exact(f1.w + bf[7]);
        __nv_bfloat162 q0 = __floats2bfloat162_rn(f0.x, f0.y);
        __nv_bfloat162 q1 = __floats2bfloat162_rn(f0.z, f0.w);
        __nv_bfloat162 q2 = __floats2bfloat162_rn(f1.x, f1.y);
        __nv_bfloat162 q3 = __floats2bfloat162_rn(f1.z, f1.w);
        uint4 pk;
        pk.x = *(unsigned*)&q0; pk.y = *(unsigned*)&q1;
        pk.z = *(unsigned*)&q2; pk.w = *(unsigned*)&q3;
        *(uint4*)(g_hb + (row0 + r) * 1024 + col0 + q * 8) = pk;
    }
}

// ---------------------------------------------------------------------------
// GEMM2: out = x3(out) + g_hb @ Wpr + bpr   [131072,1024] x [1024,256], NCH=16
// ---------------------------------------------------------------------------
__global__ void __launch_bounds__(128, 2)
gemm2_kernel(const float* __restrict__ bpr, float* __restrict__ out) {
    extern __shared__ __align__(16) char sm[];
    int tid  = threadIdx.x;
    int warp = tid >> 5;
    int wm = warp & 1, wn = warp >> 1;
    size_t row0 = (size_t)(blockIdx.x >> 1) * 128;
    int col0 = (blockIdx.x & 1) * 128;

    wmma::fragment<wmma::accumulator, 16, 16, 16, float> c[4][4];
    #pragma unroll
    for (int m = 0; m < 4; m++)
        #pragma unroll
        for (int n = 0; n < 4; n++) wmma::fill_fragment(c[m][n], 0.f);

    GEMM_FILL(sm, 0, 0, g_hb, 1024, g_wprb, 256); CP_COMMIT();
    GEMM_FILL(sm, 1, 1, g_hb, 1024, g_wprb, 256); CP_COMMIT();

    for (int kt = 0; kt < 16; kt++) {
        CP_WAIT1();
        __syncthreads();
        GEMM_COMPUTE(sm, kt & 1);
        __syncthreads();
        if (kt + 2 < 16) { GEMM_FILL(sm, kt & 1, kt + 2, g_hb, 1024, g_wprb, 256); }
        CP_COMMIT();
    }

    // epilogue: out = x3(out) + acc + bpr
    CP_WAIT0();
    __syncthreads();
    float* S = (float*)sm;
    float* Sp = S + (wm * 64) * LDS + wn * 64;
    #pragma unroll
    for (int m = 0; m < 4; m++)
        #pragma unroll
        for (int n = 0; n < 4; n++)
            wmma::store_matrix_sync(Sp + (m * 16) * LDS + n * 16, c[m][n], LDS, wmma::mem_row_major);
    __syncthreads();
    #pragma unroll
    for (int j = 0; j < 16; j++) {
        int cc = tid + j * 128, r = cc >> 4, q = cc & 15;
        const float* Sr = S + r * LDS + q * 8;
        float* og = out + (row0 + r) * DD + col0 + q * 8;
        const float* bp = bpr + col0 + q * 8;
        float4 f0 = *(const float4*)(Sr);
        float4 f1 = *(const float4*)(Sr + 4);
        float4 x0 = *(const float4*)(og);
        float4 x1 = *(const float4*)(og + 4);
        f0.x += x0.x + bp[0]; f0.y += x0.y + bp[1]; f0.z += x0.z + bp[2]; f0.w += x0.w + bp[3];
        f1.x += x1.x + bp[4]; f1.y += x1.y + bp[5]; f1.z += x1.z + bp[6]; f1.w += x1.w + bp[7];
        *(float4*)(og)     = f0;
        *(float4*)(og + 4) = f1;
    }
}

// ---------------------------------------------------------------------------
extern "C" void kernel_launch(void* const* d_in, const int* in_sizes, int n_in,
                              void* d_out, int out_size) {
    const float* x    = (const float*)d_in[0];
    const float* cx   = (const float*)d_in[1];
    const float* ln1w = (const float*)d_in[2];
    const float* ln1b = (const float*)d_in[3];
    // d_in[4]=wq, d_in[5]=bq: unused (uniform softmax over equal logits; V constant over keys)
    const float* wkv  = (const float*)d_in[6];
    const float* bkv  = (const float*)d_in[7];
    const float* wo   = (const float*)d_in[8];
    const float* bo   = (const float*)d_in[9];
    const float* ln2w = (const float*)d_in[10];
    const float* ln2b = (const float*)d_in[11];
    const float* wfc  = (const float*)d_in[12];
    const float* bfc  = (const float*)d_in[13];
    const float* wpr  = (const float*)d_in[14];
    const float* bpr  = (const float*)d_in[15];
    float* out = (float*)d_out;

    cudaFuncSetAttribute(gemm1_kernel, cudaFuncAttributeMaxDynamicSharedMemorySize, SMEM_PIPE);
    cudaFuncSetAttribute(gemm2_kernel, cudaFuncAttributeMaxDynamicSharedMemorySize, SMEM_PIPE);

    prep_kernel<<<512, 256>>>(wfc, wpr, cx, wkv, bkv, wo, bo);
    ln_kernel<<<16384, 256>>>(x, ln1w, ln1b, ln2w, ln2b, out);
    gemm1_kernel<<<8192, 128, SMEM_PIPE>>>(bfc);
    gemm2_kernel<<<2048, 128, SMEM_PIPE>>>(bpr, out);
}